// round 1
// baseline (speedup 1.0000x reference)
#include <cuda_runtime.h>

#define NB 32
#define NS 2048
#define ND 2048
#define NK 6
#define NT 256   // threads per block (8 warps)

__global__ __launch_bounds__(NT, 1)
void query_token_probe_kernel(const float* __restrict__ hs,
                              const float* __restrict__ W,
                              const float* __restrict__ bias,
                              const int*   __restrict__ input_ids,
                              const int*   __restrict__ attn_mask,
                              const int*   __restrict__ token_ids,
                              float*       __restrict__ out) {
    const int b   = blockIdx.x;
    const int tid = threadIdx.x;
    const int wid = tid >> 5;
    const int lid = tid & 31;

    // --- Phase 1: scan ids/mask for last_valid and last_match[k] ---
    int tk[NK];
#pragma unroll
    for (int k = 0; k < NK; k++) tk[k] = token_ids[k];

    const int* ids = input_ids + (size_t)b * NS;
    const int* msk = attn_mask + (size_t)b * NS;

    int lv = -1;          // last valid position seen by this thread
    int lm[NK];
#pragma unroll
    for (int k = 0; k < NK; k++) lm[k] = -1;

    // block-strided: i strictly increases per thread, so overwrite == max
    for (int i = tid; i < NS; i += NT) {
        int m = msk[i];
        if (m > 0) {
            lv = i;
            int id = ids[i];
#pragma unroll
            for (int k = 0; k < NK; k++)
                if (id == tk[k]) lm[k] = i;
        }
    }

    // warp-level max reduce of 7 quantities
#pragma unroll
    for (int off = 16; off > 0; off >>= 1) {
        lv = max(lv, __shfl_xor_sync(0xffffffffu, lv, off));
#pragma unroll
        for (int k = 0; k < NK; k++)
            lm[k] = max(lm[k], __shfl_xor_sync(0xffffffffu, lm[k], off));
    }

    __shared__ int s_part[NK + 1][NT / 32];  // [quantity][warp]
    __shared__ int s_red[NK + 1];
    if (lid == 0) {
        s_part[0][wid] = lv;
#pragma unroll
        for (int k = 0; k < NK; k++) s_part[1 + k][wid] = lm[k];
    }
    __syncthreads();
    if (tid < NK + 1) {
        int v = -1;
#pragma unroll
        for (int w = 0; w < NT / 32; w++) v = max(v, s_part[tid][w]);
        s_red[tid] = v;
    }
    __syncthreads();

    const int  last_valid = s_red[0];
    const bool has_valid  = (last_valid >= 0);

    // --- Phase 2: warp k does dot(hs[b, pos_k, :], W[k]) ---
    if (wid < NK) {
        const int k = wid;
        int fp = s_red[1 + k];
        if (fp < 0) fp = last_valid;
        int pos = fp < 0 ? 0 : (fp > NS - 1 ? NS - 1 : fp);

        const float4* __restrict__ hrow =
            (const float4*)(hs + ((size_t)b * NS + (size_t)pos) * ND);
        const float4* __restrict__ wrow = (const float4*)(W + (size_t)k * ND);

        float sum = 0.f;
#pragma unroll
        for (int i = lid; i < ND / 4; i += 32) {   // 16 iterations
            float4 h = hrow[i];
            float4 w = wrow[i];
            sum += h.x * w.x + h.y * w.y + h.z * w.z + h.w * w.w;
        }
#pragma unroll
        for (int off = 16; off > 0; off >>= 1)
            sum += __shfl_xor_sync(0xffffffffu, sum, off);

        if (lid == 0)
            out[b * NK + k] = has_valid ? (sum + bias[k]) : 0.f;
    }
}

extern "C" void kernel_launch(void* const* d_in, const int* in_sizes, int n_in,
                              void* d_out, int out_size) {
    const float* hs        = (const float*)d_in[0];
    const float* W         = (const float*)d_in[1];
    const float* bias      = (const float*)d_in[2];
    const int*   input_ids = (const int*)d_in[3];
    const int*   attn_mask = (const int*)d_in[4];
    const int*   token_ids = (const int*)d_in[5];
    float*       out       = (float*)d_out;

    query_token_probe_kernel<<<NB, NT>>>(hs, W, bias, input_ids, attn_mask,
                                         token_ids, out);
}

// round 2
// speedup vs baseline: 1.3462x; 1.3462x over previous
#include <cuda_runtime.h>

#define NB 32
#define NS 2048
#define ND 2048
#define NK 6
#define NT 512   // threads per block (16 warps)

__global__ __launch_bounds__(NT, 1)
void query_token_probe_kernel(const float* __restrict__ hs,
                              const float* __restrict__ W,
                              const float* __restrict__ bias,
                              const int*   __restrict__ input_ids,
                              const int*   __restrict__ attn_mask,
                              const int*   __restrict__ token_ids,
                              float*       __restrict__ out) {
    const int b   = blockIdx.x;
    const int tid = threadIdx.x;
    const int wid = tid >> 5;
    const int lid = tid & 31;

    __shared__ int   s_part[NK + 1][NT / 32];
    __shared__ int   s_red[NK + 1];
    __shared__ float s_acc[NK][2];

    // --- Phase 1: one int4 of mask + one int4 of ids per thread, issued together ---
    int tk[NK];
#pragma unroll
    for (int k = 0; k < NK; k++) tk[k] = token_ids[k];

    const int4 m4 = ((const int4*)(attn_mask + (size_t)b * NS))[tid];
    const int4 i4 = ((const int4*)(input_ids + (size_t)b * NS))[tid];

    const int base = tid * 4;
    int lv = -1;
    int lm[NK];
#pragma unroll
    for (int k = 0; k < NK; k++) lm[k] = -1;

    const int mv[4] = {m4.x, m4.y, m4.z, m4.w};
    const int iv[4] = {i4.x, i4.y, i4.z, i4.w};
#pragma unroll
    for (int j = 0; j < 4; j++) {
        if (mv[j] > 0) {
            lv = base + j;                 // j increasing -> overwrite == max
            const int id = iv[j];
#pragma unroll
            for (int k = 0; k < NK; k++)
                if (id == tk[k]) lm[k] = base + j;
        }
    }

    // warp max-reduce of 7 quantities
#pragma unroll
    for (int off = 16; off > 0; off >>= 1) {
        lv = max(lv, __shfl_xor_sync(0xffffffffu, lv, off));
#pragma unroll
        for (int k = 0; k < NK; k++)
            lm[k] = max(lm[k], __shfl_xor_sync(0xffffffffu, lm[k], off));
    }
    if (lid == 0) {
        s_part[0][wid] = lv;
#pragma unroll
        for (int k = 0; k < NK; k++) s_part[1 + k][wid] = lm[k];
    }
    __syncthreads();
    if (tid < NK + 1) {
        int v = -1;
#pragma unroll
        for (int w = 0; w < NT / 32; w++) v = max(v, s_part[tid][w]);
        s_red[tid] = v;
    }
    __syncthreads();

    const int  last_valid = s_red[0];
    const bool has_valid  = (last_valid >= 0);

    // --- Phase 2: 2 warps per direction k (warps 0..11) ---
    if (wid < 2 * NK) {
        const int k    = wid >> 1;
        const int half = wid & 1;

        int fp = s_red[1 + k];
        if (fp < 0) fp = last_valid;
        int pos = fp < 0 ? 0 : (fp > NS - 1 ? NS - 1 : fp);

        const float4* __restrict__ hrow =
            (const float4*)(hs + ((size_t)b * NS + (size_t)pos) * ND) + half * (ND / 8);
        const float4* __restrict__ wrow =
            (const float4*)(W + (size_t)k * ND) + half * (ND / 8);

        float sum = 0.f;
#pragma unroll
        for (int i = lid; i < ND / 8; i += 32) {   // 8 iterations, all independent
            const float4 h = hrow[i];
            const float4 w = wrow[i];
            sum += h.x * w.x + h.y * w.y + h.z * w.z + h.w * w.w;
        }
#pragma unroll
        for (int off = 16; off > 0; off >>= 1)
            sum += __shfl_xor_sync(0xffffffffu, sum, off);
        if (lid == 0) s_acc[k][half] = sum;
    }
    __syncthreads();

    if (tid < NK)
        out[b * NK + tid] = has_valid ? (s_acc[tid][0] + s_acc[tid][1] + bias[tid])
                                      : 0.f;
}

extern "C" void kernel_launch(void* const* d_in, const int* in_sizes, int n_in,
                              void* d_out, int out_size) {
    const float* hs        = (const float*)d_in[0];
    const float* W         = (const float*)d_in[1];
    const float* bias      = (const float*)d_in[2];
    const int*   input_ids = (const int*)d_in[3];
    const int*   attn_mask = (const int*)d_in[4];
    const int*   token_ids = (const int*)d_in[5];
    float*       out       = (float*)d_out;

    query_token_probe_kernel<<<NB, NT>>>(hs, W, bias, input_ids, attn_mask,
                                         token_ids, out);
}